// round 15
// baseline (speedup 1.0000x reference)
#include <cuda_runtime.h>
#include <cuda_bf16.h>
#include <math.h>
#include <stdint.h>

#define NNODES 16000
#define DIN    256
#define HD     256
#define NH     8
#define NEDGES 256000

// ---------------- device scratch ----------------
__device__ float g_q[NNODES * HD];
__device__ float g_k[NNODES * HD];
__device__ float g_v[NNODES * HD];
__device__ float g_wV[NNODES * HD];
__device__ float g_z[NNODES * NH];
// tf32 weight images in mma-fragment order:
// [mat][ks 0..31][nb 0..31][lane 0..31][2]  (b0,b1) ; mat: 0=Wq 1=Wk 2=Wv 3=We
__device__ uint32_t g_Btf[4][32 * 32 * 32 * 2];

// ---------------- helpers ----------------
__device__ __forceinline__ uint32_t f2tf32(float f) {
    uint32_t r;
    asm("cvt.rna.tf32.f32 %0, %1;" : "=r"(r) : "f"(f));
    return r;
}
__device__ __forceinline__ void mma_tf32(float* d, const uint32_t* a, const uint32_t* b) {
    asm volatile(
        "mma.sync.aligned.m16n8k8.row.col.f32.tf32.tf32.f32 "
        "{%0,%1,%2,%3}, {%4,%5,%6,%7}, {%8,%9}, {%0,%1,%2,%3};"
        : "+f"(d[0]), "+f"(d[1]), "+f"(d[2]), "+f"(d[3])
        : "r"(a[0]), "r"(a[1]), "r"(a[2]), "r"(a[3]), "r"(b[0]), "r"(b[1]));
}
__device__ __forceinline__ uint32_t smem_u32(const void* p) {
    uint32_t a;
    asm("{ .reg .u64 t; cvta.to.shared.u64 t, %1; cvt.u32.u64 %0, t; }" : "=r"(a) : "l"(p));
    return a;
}
__device__ __forceinline__ void cp_async16(uint32_t dst, const void* src) {
    asm volatile("cp.async.cg.shared.global [%0], [%1], 16;" :: "r"(dst), "l"(src));
}
__device__ __forceinline__ void red_v4(float* p, float4 v) {
    asm volatile("red.global.add.v4.f32 [%0], {%1,%2,%3,%4};"
                 :: "l"(p), "f"(v.x), "f"(v.y), "f"(v.z), "f"(v.w) : "memory");
}
#define CP_COMMIT asm volatile("cp.async.commit_group;" ::: "memory")
#define CP_WAIT0  asm volatile("cp.async.wait_group 0;" ::: "memory")

// SMEM layout (bytes).
// A: 32 rows x 32 k fp32(tf32), stride 144B -> 4608 per buf, x2
// B: fragment-ordered chunk 32768 per buf, x2
// Alpha staging (epilogue, reuses A/B region): 32 x 264 floats = 33792
#define SM_SRC   0
#define SM_DST   128
#define SM_DIST  256
#define SM_A     512
#define ABUF     4608
#define A_STRIDE 144
#define SM_B     9728
#define BBUF     32768
#define SM_ALPHA 512
#define ALPHA_STRIDE 264
#define SM_TOTAL 75264

// ---------------------------------------------------------------------------
__global__ void zero_kernel(const float4* __restrict__ coords4, float4* __restrict__ cout4) {
    int i = blockIdx.x * blockDim.x + threadIdx.x;
    float4 z4 = make_float4(0.f, 0.f, 0.f, 0.f);
    if (i < NNODES * HD / 4) ((float4*)g_wV)[i] = z4;
    if (i < NNODES * NH / 4) ((float4*)g_z)[i] = z4;
    if (i < NNODES * 3 / 4)  cout4[i] = coords4[i];
}

// ---------------------------------------------------------------------------
// Weight prep: W[k][n] fp32 -> tf32 fragment-ordered image.
// ---------------------------------------------------------------------------
__global__ void prep_weights(const float* __restrict__ Wq, const float* __restrict__ Wk,
                             const float* __restrict__ Wv, const float* __restrict__ We) {
    int t = blockIdx.x * blockDim.x + threadIdx.x;
    if (t >= 4 * 32768) return;
    int mat = t >> 15;
    int rem = t & 32767;
    int ks = rem >> 10;
    int nb = (rem >> 5) & 31;
    int tt = rem & 31;
    const float* W = mat == 0 ? Wq : mat == 1 ? Wk : mat == 2 ? Wv : We;
    int k = ks * 8 + (tt & 3);
    int n = nb * 8 + (tt >> 2);
    g_Btf[mat][rem * 2 + 0] = f2tf32(W[k * HD + n]);
    g_Btf[mat][rem * 2 + 1] = f2tf32(W[(k + 4) * HD + n]);
}

// ---------------------------------------------------------------------------
// A convert+store: thread r = tid>>3 (row 0..31), u = tid&7 (4-k quad).
// ---------------------------------------------------------------------------
__device__ __forceinline__ void convert_store_A(char* smem, int buf, int tid, float4 f) {
    int r = tid >> 3, u = tid & 7;
    uint32_t c0 = f2tf32(f.x), c1 = f2tf32(f.y), c2 = f2tf32(f.z), c3 = f2tf32(f.w);
    *(uint4*)(smem + SM_A + buf * ABUF + r * A_STRIDE + u * 16) = make_uint4(c0, c1, c2, c3);
}

// ---------------------------------------------------------------------------
// GEMM mainloop: acc[2][4][4] += tf32( A[m0:32, :256] @ W[0:256]^T )
// 256 threads, 8 warps (1 m x 8 n); warp tile 32 x 32. Double-buffered.
// ---------------------------------------------------------------------------
__device__ __forceinline__ void gemm_tile(char* smem, uint32_t sb,
                                          const float* __restrict__ A, int m0,
                                          int mat, int tid, float acc[2][4][4]) {
    int lane = tid & 31, w = tid >> 5;
    const char* Btf = (const char*)g_Btf[mat];
    int r = tid >> 3, u = tid & 7;

    uint32_t aFrag = (uint32_t)((lane >> 2) * A_STRIDE + (lane & 3) * 4);
    uint32_t bFrag = (uint32_t)((w * 4) * 256 + lane * 8);

    // prologue: chunk 0
    {
        float4 f = *(const float4*)(A + (size_t)(m0 + r) * DIN + u * 4);
        #pragma unroll
        for (int i = 0; i < 8; ++i) {
            uint32_t off = (uint32_t)(tid + 256 * i) * 16;
            cp_async16(sb + SM_B + off, Btf + off);
        }
        CP_COMMIT;
        convert_store_A(smem, 0, tid, f);
        CP_WAIT0;
        __syncthreads();
    }

    for (int kc = 0; kc < 8; ++kc) {
        int cur = kc & 1, nxt = cur ^ 1;
        float4 f;
        if (kc < 7) {
            f = *(const float4*)(A + (size_t)(m0 + r) * DIN + (kc + 1) * 32 + u * 4);
            const char* bsrc = Btf + (size_t)(kc + 1) * BBUF;
            #pragma unroll
            for (int i = 0; i < 8; ++i) {
                uint32_t off = (uint32_t)(tid + 256 * i) * 16;
                cp_async16(sb + SM_B + nxt * BBUF + off, bsrc + off);
            }
            CP_COMMIT;
        }

        uint32_t aBase = sb + SM_A + cur * ABUF + aFrag;
        uint32_t bBase = sb + SM_B + cur * BBUF + bFrag;
        #pragma unroll
        for (int ksl = 0; ksl < 4; ++ksl) {
            uint32_t a[2][4];
            #pragma unroll
            for (int mf = 0; mf < 2; ++mf) {
                uint32_t ad = aBase + (uint32_t)(mf * 16 * A_STRIDE + ksl * 32);
                asm volatile("ld.shared.b32 %0, [%1];" : "=r"(a[mf][0]) : "r"(ad));
                asm volatile("ld.shared.b32 %0, [%1];" : "=r"(a[mf][1]) : "r"(ad + 8 * A_STRIDE));
                asm volatile("ld.shared.b32 %0, [%1];" : "=r"(a[mf][2]) : "r"(ad + 16));
                asm volatile("ld.shared.b32 %0, [%1];" : "=r"(a[mf][3]) : "r"(ad + 8 * A_STRIDE + 16));
            }
            #pragma unroll
            for (int nf = 0; nf < 4; ++nf) {
                uint32_t b[2];
                uint32_t bd = bBase + (uint32_t)(ksl * 8192 + nf * 256);
                asm volatile("ld.shared.v2.b32 {%0,%1}, [%2];" : "=r"(b[0]), "=r"(b[1]) : "r"(bd));
                mma_tf32(acc[0][nf], a[0], b);
                mma_tf32(acc[1][nf], a[1], b);
            }
        }

        if (kc < 7) {
            convert_store_A(smem, nxt, tid, f);
            CP_WAIT0;
            __syncthreads();
        }
    }
}

// ---------------------------------------------------------------------------
// QKV GEMM. grid (500, 3), 256 threads. CTA tile 32 x 256.
// ---------------------------------------------------------------------------
__global__ __launch_bounds__(256, 3) void qkv_mm(const float* __restrict__ x) {
    extern __shared__ char smem[];
    uint32_t sb = smem_u32(smem);
    int tid = threadIdx.x;
    int m0 = blockIdx.x * 32;
    int mat = blockIdx.y;

    float acc[2][4][4];
    #pragma unroll
    for (int mf = 0; mf < 2; ++mf)
        #pragma unroll
        for (int nf = 0; nf < 4; ++nf)
            #pragma unroll
            for (int p = 0; p < 4; ++p) acc[mf][nf][p] = 0.0f;

    gemm_tile(smem, sb, x, m0, mat, tid, acc);

    int lane = tid & 31, w = tid >> 5;
    int qrow = lane >> 2, qcol = lane & 3;
    float* out = mat == 0 ? g_q : mat == 1 ? g_k : g_v;

    #pragma unroll
    for (int mf = 0; mf < 2; ++mf) {
        int r0 = m0 + mf * 16 + qrow;
        #pragma unroll
        for (int nf = 0; nf < 4; ++nf) {
            int c = w * 32 + nf * 8 + qcol * 2;
            *(float2*)(out + (size_t)r0 * HD + c)       = make_float2(acc[mf][nf][0], acc[mf][nf][1]);
            *(float2*)(out + (size_t)(r0 + 8) * HD + c) = make_float2(acc[mf][nf][2], acc[mf][nf][3]);
        }
    }
}

// ---------------------------------------------------------------------------
// Edge GEMM + transposed fused epilogue. grid 8000, 256 threads.
// Each CTA: 32 edges x 256 cols (all 8 heads).
// ---------------------------------------------------------------------------
__global__ __launch_bounds__(256, 3) void edge_mm(const float* __restrict__ edge_attr,
                                                  const int* __restrict__ ei,
                                                  const float* __restrict__ coords,
                                                  const float* __restrict__ We,
                                                  float* __restrict__ eout) {
    extern __shared__ char smem[];
    uint32_t sb = smem_u32(smem);
    int tid = threadIdx.x;
    int m0 = blockIdx.x * 32;

    int*   sSrc = (int*)(smem + SM_SRC);
    int*   sDst = (int*)(smem + SM_DST);
    float* sDist = (float*)(smem + SM_DIST);

    if (tid < 32) {
        int s = ei[m0 + tid];
        int d = ei[NEDGES + m0 + tid];
        sSrc[tid] = s; sDst[tid] = d;
        float dx = coords[3 * s + 0] - coords[3 * d + 0];
        float dy = coords[3 * s + 1] - coords[3 * d + 1];
        float dz = coords[3 * s + 2] - coords[3 * d + 2];
        sDist[tid] = 0.1f * sqrtf(dx * dx + dy * dy + dz * dz);
    }
    __syncthreads();

    float acc[2][4][4];
    #pragma unroll
    for (int mf = 0; mf < 2; ++mf)
        #pragma unroll
        for (int nf = 0; nf < 4; ++nf)
            #pragma unroll
            for (int p = 0; p < 4; ++p) acc[mf][nf][p] = 0.0f;

    gemm_tile(smem, sb, edge_attr, m0, 3, tid, acc);

    int lane = tid & 31, w = tid >> 5;
    int qrow = lane >> 2, qcol = lane & 3;

    // ---- stage raw acc into smem alpha tile [32][264] (reuses A/B bufs) ----
    __syncthreads();
    float* alpha = (float*)(smem + SM_ALPHA);
    #pragma unroll
    for (int mf = 0; mf < 2; ++mf) {
        int r0 = mf * 16 + qrow;
        #pragma unroll
        for (int nf = 0; nf < 4; ++nf) {
            int c = w * 32 + nf * 8 + qcol * 2;
            *(float2*)&alpha[r0 * ALPHA_STRIDE + c]       = make_float2(acc[mf][nf][0], acc[mf][nf][1]);
            *(float2*)&alpha[(r0 + 8) * ALPHA_STRIDE + c] = make_float2(acc[mf][nf][2], acc[mf][nf][3]);
        }
    }
    __syncthreads();

    // ---- transposed epilogue: warp w handles edges w*4 .. w*4+3 ----
    const float invs = 0.17677669529663687f;   // 1/sqrt(32)
    int c0 = lane * 4;
    int c1 = 128 + lane * 4;
    int h0 = lane >> 3;
    float4 wlA = *(const float4*)(We + (size_t)DIN * HD + c0);
    float4 wlB = *(const float4*)(We + (size_t)DIN * HD + c1);

    #pragma unroll
    for (int i = 0; i < 4; ++i) {
        int e = w * 4 + i;
        int src = sSrc[e], dst = sDst[e];
        float de = sDist[e];
        const float* krow = g_k + (size_t)src * HD;
        const float* qrow_p = g_q + (size_t)dst * HD;
        float4 dA = *(const float4*)&alpha[e * ALPHA_STRIDE + c0];
        float4 dB = *(const float4*)&alpha[e * ALPHA_STRIDE + c1];
        float4 kA = *(const float4*)(krow + c0);
        float4 kB = *(const float4*)(krow + c1);
        float4 qA = *(const float4*)(qrow_p + c0);
        float4 qB = *(const float4*)(qrow_p + c1);
        float4 aA, aB;
        float s;
        s = fminf(5.0f, fmaxf(-5.0f, kA.x * qA.x * invs)); aA.x = s * (dA.x + de * wlA.x);
        s = fminf(5.0f, fmaxf(-5.0f, kA.y * qA.y * invs)); aA.y = s * (dA.y + de * wlA.y);
        s = fminf(5.0f, fmaxf(-5.0f, kA.z * qA.z * invs)); aA.z = s * (dA.z + de * wlA.z);
        s = fminf(5.0f, fmaxf(-5.0f, kA.w * qA.w * invs)); aA.w = s * (dA.w + de * wlA.w);
        s = fminf(5.0f, fmaxf(-5.0f, kB.x * qB.x * invs)); aB.x = s * (dB.x + de * wlB.x);
        s = fminf(5.0f, fmaxf(-5.0f, kB.y * qB.y * invs)); aB.y = s * (dB.y + de * wlB.y);
        s = fminf(5.0f, fmaxf(-5.0f, kB.z * qB.z * invs)); aB.z = s * (dB.z + de * wlB.z);
        s = fminf(5.0f, fmaxf(-5.0f, kB.w * qB.w * invs)); aB.w = s * (dB.w + de * wlB.w);
        float* eo = eout + (size_t)(m0 + e) * HD;
        *(float4*)(eo + c0) = aA;
        *(float4*)(eo + c1) = aB;

        float pA = (aA.x + aA.y) + (aA.z + aA.w);
        float pB = (aB.x + aB.y) + (aB.z + aB.w);
        pA += __shfl_xor_sync(0xffffffffu, pA, 1);
        pB += __shfl_xor_sync(0xffffffffu, pB, 1);
        pA += __shfl_xor_sync(0xffffffffu, pA, 2);
        pB += __shfl_xor_sync(0xffffffffu, pB, 2);
        pA += __shfl_xor_sync(0xffffffffu, pA, 4);
        pB += __shfl_xor_sync(0xffffffffu, pB, 4);
        float axA = expf(fminf(5.0f, fmaxf(-5.0f, pA)));
        float axB = expf(fminf(5.0f, fmaxf(-5.0f, pB)));

        const float* vrow = g_v + (size_t)src * HD;
        float4 vA = *(const float4*)(vrow + c0);
        float4 vB = *(const float4*)(vrow + c1);
        float* wv = g_wV + (size_t)dst * HD;
        red_v4(wv + c0, make_float4(vA.x * axA, vA.y * axA, vA.z * axA, vA.w * axA));
        red_v4(wv + c1, make_float4(vB.x * axB, vB.y * axB, vB.z * axB, vB.w * axB));
        if ((lane & 7) == 0) {
            atomicAdd(&g_z[(size_t)dst * NH + h0], axA);
            atomicAdd(&g_z[(size_t)dst * NH + 4 + h0], axB);
        }
    }
}

// ---------------------------------------------------------------------------
__global__ void finalize_kernel(float4* __restrict__ hout4) {
    int i = blockIdx.x * blockDim.x + threadIdx.x;
    if (i < NNODES * HD / 4) {
        int base = i * 4;
        int n = base >> 8;
        int h = (base & 255) >> 5;
        float4 wv = ((const float4*)g_wV)[i];
        float inv = 1.0f / (g_z[n * NH + h] + 1e-6f);
        hout4[i] = make_float4(wv.x * inv, wv.y * inv, wv.z * inv, wv.w * inv);
    }
}

// ---------------------------------------------------------------------------
extern "C" void kernel_launch(void* const* d_in, const int* in_sizes, int n_in,
                              void* d_out, int out_size)
{
    const float* x         = (const float*)d_in[0];
    const float* edge_attr = (const float*)d_in[1];
    const int*   ei        = (const int*)d_in[2];
    const float* coords    = (const float*)d_in[3];
    const float* Wq        = (const float*)d_in[4];
    const float* Wk        = (const float*)d_in[5];
    const float* Wv        = (const float*)d_in[6];
    const float* We        = (const float*)d_in[7];

    float* out  = (float*)d_out;
    float* hout = out;
    float* eout = out + (size_t)NNODES * HD;
    float* cout = eout + (size_t)NEDGES * HD;

    static bool attr_set = false;
    if (!attr_set) {
        cudaFuncSetAttribute(qkv_mm,  cudaFuncAttributeMaxDynamicSharedMemorySize, SM_TOTAL);
        cudaFuncSetAttribute(edge_mm, cudaFuncAttributeMaxDynamicSharedMemorySize, SM_TOTAL);
        attr_set = true;
    }

    zero_kernel<<<(NNODES * HD / 4 + 255) / 256, 256>>>((const float4*)coords, (float4*)cout);
    prep_weights<<<512, 256>>>(Wq, Wk, Wv, We);
    qkv_mm<<<dim3(500, 3), 256, SM_TOTAL>>>(x);
    edge_mm<<<8000, 256, SM_TOTAL>>>(edge_attr, ei, coords, We, eout);
    finalize_kernel<<<(NNODES * HD / 4 + 255) / 256, 256>>>((float4*)hout);
}

// round 16
// speedup vs baseline: 1.0804x; 1.0804x over previous
#include <cuda_runtime.h>
#include <cuda_bf16.h>
#include <math.h>
#include <stdint.h>

#define NNODES 16000
#define DIN    256
#define HD     256
#define NH     8
#define NEDGES 256000

// ---------------- device scratch ----------------
__device__ float g_q[NNODES * HD];
__device__ float g_k[NNODES * HD];
__device__ float g_v[NNODES * HD];
__device__ float g_wV[NNODES * HD];
__device__ float g_z[NNODES * NH];
// tf32 weight images in mma-fragment order:
// [mat][ks 0..31][nb 0..31][lane 0..31][2]  (b0,b1) ; mat: 0=Wq 1=Wk 2=Wv 3=We
__device__ uint32_t g_Btf[4][32 * 32 * 32 * 2];

// ---------------- helpers ----------------
__device__ __forceinline__ uint32_t f2tf32(float f) {
    uint32_t r;
    asm("cvt.rna.tf32.f32 %0, %1;" : "=r"(r) : "f"(f));
    return r;
}
__device__ __forceinline__ void mma_tf32(float* d, const uint32_t* a, const uint32_t* b) {
    asm volatile(
        "mma.sync.aligned.m16n8k8.row.col.f32.tf32.tf32.f32 "
        "{%0,%1,%2,%3}, {%4,%5,%6,%7}, {%8,%9}, {%0,%1,%2,%3};"
        : "+f"(d[0]), "+f"(d[1]), "+f"(d[2]), "+f"(d[3])
        : "r"(a[0]), "r"(a[1]), "r"(a[2]), "r"(a[3]), "r"(b[0]), "r"(b[1]));
}
__device__ __forceinline__ uint32_t smem_u32(const void* p) {
    uint32_t a;
    asm("{ .reg .u64 t; cvta.to.shared.u64 t, %1; cvt.u32.u64 %0, t; }" : "=r"(a) : "l"(p));
    return a;
}
__device__ __forceinline__ void cp_async16(uint32_t dst, const void* src) {
    asm volatile("cp.async.cg.shared.global [%0], [%1], 16;" :: "r"(dst), "l"(src));
}
__device__ __forceinline__ void red_v4(float* p, float4 v) {
    asm volatile("red.global.add.v4.f32 [%0], {%1,%2,%3,%4};"
                 :: "l"(p), "f"(v.x), "f"(v.y), "f"(v.z), "f"(v.w) : "memory");
}
__device__ __forceinline__ float4 ldcs4(const float4* p) {
    float4 v;
    asm volatile("ld.global.cs.v4.f32 {%0,%1,%2,%3}, [%4];"
                 : "=f"(v.x), "=f"(v.y), "=f"(v.z), "=f"(v.w) : "l"(p));
    return v;
}
__device__ __forceinline__ void stcs4(float4* p, float4 v) {
    asm volatile("st.global.cs.v4.f32 [%0], {%1,%2,%3,%4};"
                 :: "l"(p), "f"(v.x), "f"(v.y), "f"(v.z), "f"(v.w) : "memory");
}
#define CP_COMMIT asm volatile("cp.async.commit_group;" ::: "memory")
#define CP_WAIT0  asm volatile("cp.async.wait_group 0;" ::: "memory")

// SMEM layout (bytes).
// A: 64 rows x 32 k fp32(tf32), stride 144B -> 9216 per buf, x2
// B: fragment-ordered chunk 32768 per buf, x2
// Alpha staging (epilogue, reuses A/B region): 64 x 264 floats = 67584
#define SM_SRC   0
#define SM_DST   256
#define SM_DIST  512
#define SM_A     1024
#define ABUF     9216
#define A_STRIDE 144
#define SM_B     19456
#define BBUF     32768
#define SM_ALPHA 1024
#define ALPHA_STRIDE 264
#define SM_TOTAL 84992

// ---------------------------------------------------------------------------
__global__ void zero_kernel(const float4* __restrict__ coords4, float4* __restrict__ cout4) {
    int i = blockIdx.x * blockDim.x + threadIdx.x;
    float4 z4 = make_float4(0.f, 0.f, 0.f, 0.f);
    if (i < NNODES * HD / 4) ((float4*)g_wV)[i] = z4;
    if (i < NNODES * NH / 4) ((float4*)g_z)[i] = z4;
    if (i < NNODES * 3 / 4)  cout4[i] = coords4[i];
}

// ---------------------------------------------------------------------------
// Weight prep: W[k][n] fp32 -> tf32 fragment-ordered image.
// ---------------------------------------------------------------------------
__global__ void prep_weights(const float* __restrict__ Wq, const float* __restrict__ Wk,
                             const float* __restrict__ Wv, const float* __restrict__ We) {
    int t = blockIdx.x * blockDim.x + threadIdx.x;
    if (t >= 4 * 32768) return;
    int mat = t >> 15;
    int rem = t & 32767;
    int ks = rem >> 10;
    int nb = (rem >> 5) & 31;
    int tt = rem & 31;
    const float* W = mat == 0 ? Wq : mat == 1 ? Wk : mat == 2 ? Wv : We;
    int k = ks * 8 + (tt & 3);
    int n = nb * 8 + (tt >> 2);
    g_Btf[mat][rem * 2 + 0] = f2tf32(W[k * HD + n]);
    g_Btf[mat][rem * 2 + 1] = f2tf32(W[(k + 4) * HD + n]);
}

// ---------------------------------------------------------------------------
// A convert+store: thread r = tid>>2 (row), u = tid&3 (8-k unit); tf32 cvt.
// ---------------------------------------------------------------------------
__device__ __forceinline__ void convert_store_A(char* smem, int buf, int tid,
                                                float4 f0, float4 f1) {
    int r = tid >> 2, u = tid & 3;
    uint32_t c[8];
    c[0] = f2tf32(f0.x); c[1] = f2tf32(f0.y); c[2] = f2tf32(f0.z); c[3] = f2tf32(f0.w);
    c[4] = f2tf32(f1.x); c[5] = f2tf32(f1.y); c[6] = f2tf32(f1.z); c[7] = f2tf32(f1.w);
    char* base = smem + SM_A + buf * ABUF + r * A_STRIDE + u * 32;
    *(uint4*)(base)      = make_uint4(c[0], c[1], c[2], c[3]);
    *(uint4*)(base + 16) = make_uint4(c[4], c[5], c[6], c[7]);
}

// ---------------------------------------------------------------------------
// GEMM mainloop: acc[2][8][4] += tf32( A[m0:64, :256] @ W[0:256]^T )
// 256 threads, 8 warps (2 m x 4 n); warp tile 32 x 64. Double-buffered.
// A loaded with .cs (streaming) hint to preserve L2 for gathers.
// ---------------------------------------------------------------------------
__device__ __forceinline__ void gemm_tile(char* smem, uint32_t sb,
                                          const float* __restrict__ A, int m0,
                                          int mat, int tid, float acc[2][8][4]) {
    int lane = tid & 31, w = tid >> 5;
    int warp_m = w & 1, warp_n = w >> 1;
    const char* Btf = (const char*)g_Btf[mat];
    int r = tid >> 2, u = tid & 3;

    uint32_t aFrag = (uint32_t)((warp_m * 32 + (lane >> 2)) * A_STRIDE + (lane & 3) * 4);
    uint32_t bFrag = (uint32_t)(((warp_n * 8) * 32 + lane) * 8);

    // prologue: chunk 0
    {
        const float4* src = (const float4*)(A + (size_t)(m0 + r) * DIN + u * 8);
        float4 f0 = ldcs4(src), f1 = ldcs4(src + 1);
        #pragma unroll
        for (int i = 0; i < 8; ++i) {
            uint32_t off = (uint32_t)(tid + 256 * i) * 16;
            cp_async16(sb + SM_B + off, Btf + off);
        }
        CP_COMMIT;
        convert_store_A(smem, 0, tid, f0, f1);
        CP_WAIT0;
        __syncthreads();
    }

    for (int kc = 0; kc < 8; ++kc) {
        int cur = kc & 1, nxt = cur ^ 1;
        float4 f0, f1;
        if (kc < 7) {
            const float4* src = (const float4*)(A + (size_t)(m0 + r) * DIN + (kc + 1) * 32 + u * 8);
            f0 = ldcs4(src); f1 = ldcs4(src + 1);
            const char* bsrc = Btf + (size_t)(kc + 1) * BBUF;
            #pragma unroll
            for (int i = 0; i < 8; ++i) {
                uint32_t off = (uint32_t)(tid + 256 * i) * 16;
                cp_async16(sb + SM_B + nxt * BBUF + off, bsrc + off);
            }
            CP_COMMIT;
        }

        uint32_t aBase = sb + SM_A + cur * ABUF + aFrag;
        uint32_t bBase = sb + SM_B + cur * BBUF + bFrag;
        #pragma unroll
        for (int ksl = 0; ksl < 4; ++ksl) {
            uint32_t a[2][4];
            #pragma unroll
            for (int mf = 0; mf < 2; ++mf) {
                uint32_t ad = aBase + (uint32_t)(mf * 16 * A_STRIDE + ksl * 32);
                asm volatile("ld.shared.b32 %0, [%1];"      : "=r"(a[mf][0]) : "r"(ad));
                asm volatile("ld.shared.b32 %0, [%1];"      : "=r"(a[mf][1]) : "r"(ad + 8 * A_STRIDE));
                asm volatile("ld.shared.b32 %0, [%1];"      : "=r"(a[mf][2]) : "r"(ad + 16));
                asm volatile("ld.shared.b32 %0, [%1];"      : "=r"(a[mf][3]) : "r"(ad + 8 * A_STRIDE + 16));
            }
            #pragma unroll
            for (int nf = 0; nf < 8; ++nf) {
                uint32_t b[2];
                uint32_t bd = bBase + (uint32_t)((ksl * 32 + nf) * 256);
                asm volatile("ld.shared.v2.b32 {%0,%1}, [%2];" : "=r"(b[0]), "=r"(b[1]) : "r"(bd));
                mma_tf32(acc[0][nf], a[0], b);
                mma_tf32(acc[1][nf], a[1], b);
            }
        }

        if (kc < 7) {
            convert_store_A(smem, nxt, tid, f0, f1);
            CP_WAIT0;
            __syncthreads();
        }
    }
}

// ---------------------------------------------------------------------------
// QKV GEMM. grid (250, 3), 256 threads. CTA tile 64 x 256.
// ---------------------------------------------------------------------------
__global__ __launch_bounds__(256, 2) void qkv_mm(const float* __restrict__ x) {
    extern __shared__ char smem[];
    uint32_t sb = smem_u32(smem);
    int tid = threadIdx.x;
    int m0 = blockIdx.x * 64;
    int mat = blockIdx.y;

    float acc[2][8][4];
    #pragma unroll
    for (int mf = 0; mf < 2; ++mf)
        #pragma unroll
        for (int nf = 0; nf < 8; ++nf)
            #pragma unroll
            for (int p = 0; p < 4; ++p) acc[mf][nf][p] = 0.0f;

    gemm_tile(smem, sb, x, m0, mat, tid, acc);

    int lane = tid & 31, w = tid >> 5;
    int warp_m = w & 1, warp_n = w >> 1;
    int qrow = lane >> 2, qcol = lane & 3;
    float* out = mat == 0 ? g_q : mat == 1 ? g_k : g_v;

    #pragma unroll
    for (int mf = 0; mf < 2; ++mf) {
        int r0 = m0 + warp_m * 32 + mf * 16 + qrow;
        #pragma unroll
        for (int nf = 0; nf < 8; ++nf) {
            int c = warp_n * 64 + nf * 8 + qcol * 2;
            *(float2*)(out + (size_t)r0 * HD + c)       = make_float2(acc[mf][nf][0], acc[mf][nf][1]);
            *(float2*)(out + (size_t)(r0 + 8) * HD + c) = make_float2(acc[mf][nf][2], acc[mf][nf][3]);
        }
    }
}

// ---------------------------------------------------------------------------
// Edge GEMM + transposed fused epilogue. grid 4000, 256 threads.
// Each CTA: 64 edges x 256 cols (all 8 heads). e_out stored with .cs hint.
// ---------------------------------------------------------------------------
__global__ __launch_bounds__(256, 2) void edge_mm(const float* __restrict__ edge_attr,
                                                  const int* __restrict__ ei,
                                                  const float* __restrict__ coords,
                                                  const float* __restrict__ We,
                                                  float* __restrict__ eout) {
    extern __shared__ char smem[];
    uint32_t sb = smem_u32(smem);
    int tid = threadIdx.x;
    int m0 = blockIdx.x * 64;

    int*   sSrc = (int*)(smem + SM_SRC);
    int*   sDst = (int*)(smem + SM_DST);
    float* sDist = (float*)(smem + SM_DIST);

    if (tid < 64) {
        int s = ei[m0 + tid];
        int d = ei[NEDGES + m0 + tid];
        sSrc[tid] = s; sDst[tid] = d;
        float dx = coords[3 * s + 0] - coords[3 * d + 0];
        float dy = coords[3 * s + 1] - coords[3 * d + 1];
        float dz = coords[3 * s + 2] - coords[3 * d + 2];
        sDist[tid] = 0.1f * sqrtf(dx * dx + dy * dy + dz * dz);
    }
    __syncthreads();

    float acc[2][8][4];
    #pragma unroll
    for (int mf = 0; mf < 2; ++mf)
        #pragma unroll
        for (int nf = 0; nf < 8; ++nf)
            #pragma unroll
            for (int p = 0; p < 4; ++p) acc[mf][nf][p] = 0.0f;

    gemm_tile(smem, sb, edge_attr, m0, 3, tid, acc);

    int lane = tid & 31, w = tid >> 5;
    int warp_m = w & 1, warp_n = w >> 1;
    int qrow = lane >> 2, qcol = lane & 3;

    // ---- stage raw acc into smem alpha tile [64][264] (reuses A/B bufs) ----
    __syncthreads();
    float* alpha = (float*)(smem + SM_ALPHA);
    #pragma unroll
    for (int mf = 0; mf < 2; ++mf) {
        int r0 = warp_m * 32 + mf * 16 + qrow;
        #pragma unroll
        for (int nf = 0; nf < 8; ++nf) {
            int c = warp_n * 64 + nf * 8 + qcol * 2;
            *(float2*)&alpha[r0 * ALPHA_STRIDE + c]       = make_float2(acc[mf][nf][0], acc[mf][nf][1]);
            *(float2*)&alpha[(r0 + 8) * ALPHA_STRIDE + c] = make_float2(acc[mf][nf][2], acc[mf][nf][3]);
        }
    }
    __syncthreads();

    // ---- transposed epilogue: warp w handles edges w*8 .. w*8+7 ----
    const float invs = 0.17677669529663687f;   // 1/sqrt(32)
    int c0 = lane * 4;
    int c1 = 128 + lane * 4;
    int h0 = lane >> 3;
    float4 wlA = *(const float4*)(We + (size_t)DIN * HD + c0);
    float4 wlB = *(const float4*)(We + (size_t)DIN * HD + c1);

    #pragma unroll 2
    for (int i = 0; i < 8; ++i) {
        int e = w * 8 + i;
        int src = sSrc[e], dst = sDst[e];
        float de = sDist[e];
        const float* krow = g_k + (size_t)src * HD;
        const float* qrow_p = g_q + (size_t)dst * HD;
        float4 dA = *(const float4*)&alpha[e * ALPHA_STRIDE + c0];
        float4 dB = *(const float4*)&alpha[e * ALPHA_STRIDE + c1];
        float4 kA = *(const float4*)(krow + c0);
        float4 kB = *(const float4*)(krow + c1);
        float4 qA = *(const float4*)(qrow_p + c0);
        float4 qB = *(const float4*)(qrow_p + c1);
        float4 aA, aB;
        float s;
        s = fminf(5.0f, fmaxf(-5.0f, kA.x * qA.x * invs)); aA.x = s * (dA.x + de * wlA.x);
        s = fminf(5.0f, fmaxf(-5.0f, kA.y * qA.y * invs)); aA.y = s * (dA.y + de * wlA.y);
        s = fminf(5.0f, fmaxf(-5.0f, kA.z * qA.z * invs)); aA.z = s * (dA.z + de * wlA.z);
        s = fminf(5.0f, fmaxf(-5.0f, kA.w * qA.w * invs)); aA.w = s * (dA.w + de * wlA.w);
        s = fminf(5.0f, fmaxf(-5.0f, kB.x * qB.x * invs)); aB.x = s * (dB.x + de * wlB.x);
        s = fminf(5.0f, fmaxf(-5.0f, kB.y * qB.y * invs)); aB.y = s * (dB.y + de * wlB.y);
        s = fminf(5.0f, fmaxf(-5.0f, kB.z * qB.z * invs)); aB.z = s * (dB.z + de * wlB.z);
        s = fminf(5.0f, fmaxf(-5.0f, kB.w * qB.w * invs)); aB.w = s * (dB.w + de * wlB.w);
        float* eo = eout + (size_t)(m0 + e) * HD;
        stcs4((float4*)(eo + c0), aA);
        stcs4((float4*)(eo + c1), aB);

        float pA = (aA.x + aA.y) + (aA.z + aA.w);
        float pB = (aB.x + aB.y) + (aB.z + aB.w);
        pA += __shfl_xor_sync(0xffffffffu, pA, 1);
        pB += __shfl_xor_sync(0xffffffffu, pB, 1);
        pA += __shfl_xor_sync(0xffffffffu, pA, 2);
        pB += __shfl_xor_sync(0xffffffffu, pB, 2);
        pA += __shfl_xor_sync(0xffffffffu, pA, 4);
        pB += __shfl_xor_sync(0xffffffffu, pB, 4);
        float axA = expf(fminf(5.0f, fmaxf(-5.0f, pA)));
        float axB = expf(fminf(5.0f, fmaxf(-5.0f, pB)));

        const float* vrow = g_v + (size_t)src * HD;
        float4 vA = *(const float4*)(vrow + c0);
        float4 vB = *(const float4*)(vrow + c1);
        float* wv = g_wV + (size_t)dst * HD;
        red_v4(wv + c0, make_float4(vA.x * axA, vA.y * axA, vA.z * axA, vA.w * axA));
        red_v4(wv + c1, make_float4(vB.x * axB, vB.y * axB, vB.z * axB, vB.w * axB));
        if ((lane & 7) == 0) {
            atomicAdd(&g_z[(size_t)dst * NH + h0], axA);
            atomicAdd(&g_z[(size_t)dst * NH + 4 + h0], axB);
        }
    }
}

// ---------------------------------------------------------------------------
__global__ void finalize_kernel(float4* __restrict__ hout4) {
    int i = blockIdx.x * blockDim.x + threadIdx.x;
    if (i < NNODES * HD / 4) {
        int base = i * 4;
        int n = base >> 8;
        int h = (base & 255) >> 5;
        float4 wv = ((const float4*)g_wV)[i];
        float inv = 1.0f / (g_z[n * NH + h] + 1e-6f);
        hout4[i] = make_float4(wv.x * inv, wv.y * inv, wv.z * inv, wv.w * inv);
    }
}

// ---------------------------------------------------------------------------
extern "C" void kernel_launch(void* const* d_in, const int* in_sizes, int n_in,
                              void* d_out, int out_size)
{
    const float* x         = (const float*)d_in[0];
    const float* edge_attr = (const float*)d_in[1];
    const int*   ei        = (const int*)d_in[2];
    const float* coords    = (const float*)d_in[3];
    const float* Wq        = (const float*)d_in[4];
    const float* Wk        = (const float*)d_in[5];
    const float* Wv        = (const float*)d_in[6];
    const float* We        = (const float*)d_in[7];

    float* out  = (float*)d_out;
    float* hout = out;
    float* eout = out + (size_t)NNODES * HD;
    float* cout = eout + (size_t)NEDGES * HD;

    static bool attr_set = false;
    if (!attr_set) {
        cudaFuncSetAttribute(qkv_mm,  cudaFuncAttributeMaxDynamicSharedMemorySize, SM_TOTAL);
        cudaFuncSetAttribute(edge_mm, cudaFuncAttributeMaxDynamicSharedMemorySize, SM_TOTAL);
        attr_set = true;
    }

    zero_kernel<<<(NNODES * HD / 4 + 255) / 256, 256>>>((const float4*)coords, (float4*)cout);
    prep_weights<<<512, 256>>>(Wq, Wk, Wv, We);
    qkv_mm<<<dim3(250, 3), 256, SM_TOTAL>>>(x);
    edge_mm<<<4000, 256, SM_TOTAL>>>(edge_attr, ei, coords, We, eout);
    finalize_kernel<<<(NNODES * HD / 4 + 255) / 256, 256>>>((float4*)hout);
}

// round 17
// speedup vs baseline: 1.1411x; 1.0562x over previous
#include <cuda_runtime.h>
#include <cuda_bf16.h>
#include <math.h>
#include <stdint.h>

#define NNODES 16000
#define DIN    256
#define HD     256
#define NH     8
#define NEDGES 256000

// ---------------- device scratch ----------------
__device__ float g_q[NNODES * HD];
__device__ float g_k[NNODES * HD];
__device__ float g_v[NNODES * HD];
__device__ float g_wV[NNODES * HD];
__device__ float g_z[NNODES * NH];
// tf32 weight images in mma-fragment order:
// [mat][ks 0..31][nb 0..31][lane 0..31][2]  (b0,b1) ; mat: 0=Wq 1=Wk 2=Wv 3=We
__device__ uint32_t g_Btf[4][32 * 32 * 32 * 2];

// ---------------- helpers ----------------
__device__ __forceinline__ uint32_t f2tf32(float f) {
    uint32_t r;
    asm("cvt.rna.tf32.f32 %0, %1;" : "=r"(r) : "f"(f));
    return r;
}
__device__ __forceinline__ void mma_tf32(float* d, const uint32_t* a, const uint32_t* b) {
    asm volatile(
        "mma.sync.aligned.m16n8k8.row.col.f32.tf32.tf32.f32 "
        "{%0,%1,%2,%3}, {%4,%5,%6,%7}, {%8,%9}, {%0,%1,%2,%3};"
        : "+f"(d[0]), "+f"(d[1]), "+f"(d[2]), "+f"(d[3])
        : "r"(a[0]), "r"(a[1]), "r"(a[2]), "r"(a[3]), "r"(b[0]), "r"(b[1]));
}
__device__ __forceinline__ uint32_t smem_u32(const void* p) {
    uint32_t a;
    asm("{ .reg .u64 t; cvta.to.shared.u64 t, %1; cvt.u32.u64 %0, t; }" : "=r"(a) : "l"(p));
    return a;
}
__device__ __forceinline__ void cp_async16(uint32_t dst, const void* src) {
    asm volatile("cp.async.cg.shared.global [%0], [%1], 16;" :: "r"(dst), "l"(src));
}
__device__ __forceinline__ void red_v4(float* p, float4 v) {
    asm volatile("red.global.add.v4.f32 [%0], {%1,%2,%3,%4};"
                 :: "l"(p), "f"(v.x), "f"(v.y), "f"(v.z), "f"(v.w) : "memory");
}
__device__ __forceinline__ float4 ldcs4(const float4* p) {
    float4 v;
    asm volatile("ld.global.cs.v4.f32 {%0,%1,%2,%3}, [%4];"
                 : "=f"(v.x), "=f"(v.y), "=f"(v.z), "=f"(v.w) : "l"(p));
    return v;
}
__device__ __forceinline__ void stcs4(float4* p, float4 v) {
    asm volatile("st.global.cs.v4.f32 [%0], {%1,%2,%3,%4};"
                 :: "l"(p), "f"(v.x), "f"(v.y), "f"(v.z), "f"(v.w) : "memory");
}
#define CP_COMMIT asm volatile("cp.async.commit_group;" ::: "memory")
#define CP_WAIT0  asm volatile("cp.async.wait_group 0;" ::: "memory")

// SMEM layout (bytes).
#define SM_SRC   0
#define SM_DST   256
#define SM_DIST  512
#define SM_A     1024
#define ABUF     9216
#define A_STRIDE 144
#define SM_B     19456
#define BBUF     32768
#define SM_ALPHA 1024
#define ALPHA_STRIDE 264
#define SM_TOTAL 84992

// ---------------------------------------------------------------------------
// init: zero accumulators + copy coords + build tf32 fragment-ordered weights
// grid 1024 x 256 threads = 262144
// ---------------------------------------------------------------------------
__global__ void init_kernel(const float4* __restrict__ coords4, float4* __restrict__ cout4,
                            const float* __restrict__ Wq, const float* __restrict__ Wk,
                            const float* __restrict__ Wv, const float* __restrict__ We) {
    int i = blockIdx.x * blockDim.x + threadIdx.x;
    float4 z4 = make_float4(0.f, 0.f, 0.f, 0.f);
    if (i < NNODES * HD / 4) ((float4*)g_wV)[i] = z4;
    if (i < NNODES * NH / 4) ((float4*)g_z)[i] = z4;
    if (i < NNODES * 3 / 4)  cout4[i] = coords4[i];
    if (i < 4 * 32768) {
        int mat = i >> 15;
        int rem = i & 32767;
        int ks = rem >> 10;
        int nb = (rem >> 5) & 31;
        int tt = rem & 31;
        const float* W = mat == 0 ? Wq : mat == 1 ? Wk : mat == 2 ? Wv : We;
        int k = ks * 8 + (tt & 3);
        int n = nb * 8 + (tt >> 2);
        g_Btf[mat][rem * 2 + 0] = f2tf32(W[k * HD + n]);
        g_Btf[mat][rem * 2 + 1] = f2tf32(W[(k + 4) * HD + n]);
    }
}

// ---------------------------------------------------------------------------
// A convert+store: thread r = tid>>2 (row), u = tid&3 (8-k unit); tf32 cvt.
// ---------------------------------------------------------------------------
__device__ __forceinline__ void convert_store_A(char* smem, int buf, int tid,
                                                float4 f0, float4 f1) {
    int r = tid >> 2, u = tid & 3;
    uint32_t c[8];
    c[0] = f2tf32(f0.x); c[1] = f2tf32(f0.y); c[2] = f2tf32(f0.z); c[3] = f2tf32(f0.w);
    c[4] = f2tf32(f1.x); c[5] = f2tf32(f1.y); c[6] = f2tf32(f1.z); c[7] = f2tf32(f1.w);
    char* base = smem + SM_A + buf * ABUF + r * A_STRIDE + u * 32;
    *(uint4*)(base)      = make_uint4(c[0], c[1], c[2], c[3]);
    *(uint4*)(base + 16) = make_uint4(c[4], c[5], c[6], c[7]);
}

// ---------------------------------------------------------------------------
// GEMM mainloop: acc[2][8][4] += tf32( A[m0:64, :256] @ W[0:256]^T )
// 256 threads, 8 warps (2 m x 4 n); warp tile 32 x 64. Double-buffered.
// ---------------------------------------------------------------------------
__device__ __forceinline__ void gemm_tile(char* smem, uint32_t sb,
                                          const float* __restrict__ A, int m0,
                                          int mat, int tid, float acc[2][8][4]) {
    int lane = tid & 31, w = tid >> 5;
    int warp_m = w & 1, warp_n = w >> 1;
    const char* Btf = (const char*)g_Btf[mat];
    int r = tid >> 2, u = tid & 3;

    uint32_t aFrag = (uint32_t)((warp_m * 32 + (lane >> 2)) * A_STRIDE + (lane & 3) * 4);
    uint32_t bFrag = (uint32_t)(((warp_n * 8) * 32 + lane) * 8);

    // prologue: chunk 0
    {
        const float4* src = (const float4*)(A + (size_t)(m0 + r) * DIN + u * 8);
        float4 f0 = ldcs4(src), f1 = ldcs4(src + 1);
        #pragma unroll
        for (int i = 0; i < 8; ++i) {
            uint32_t off = (uint32_t)(tid + 256 * i) * 16;
            cp_async16(sb + SM_B + off, Btf + off);
        }
        CP_COMMIT;
        convert_store_A(smem, 0, tid, f0, f1);
        CP_WAIT0;
        __syncthreads();
    }

    for (int kc = 0; kc < 8; ++kc) {
        int cur = kc & 1, nxt = cur ^ 1;
        float4 f0, f1;
        if (kc < 7) {
            const float4* src = (const float4*)(A + (size_t)(m0 + r) * DIN + (kc + 1) * 32 + u * 8);
            f0 = ldcs4(src); f1 = ldcs4(src + 1);
            const char* bsrc = Btf + (size_t)(kc + 1) * BBUF;
            #pragma unroll
            for (int i = 0; i < 8; ++i) {
                uint32_t off = (uint32_t)(tid + 256 * i) * 16;
                cp_async16(sb + SM_B + nxt * BBUF + off, bsrc + off);
            }
            CP_COMMIT;
        }

        uint32_t aBase = sb + SM_A + cur * ABUF + aFrag;
        uint32_t bBase = sb + SM_B + cur * BBUF + bFrag;
        #pragma unroll
        for (int ksl = 0; ksl < 4; ++ksl) {
            uint32_t a[2][4];
            #pragma unroll
            for (int mf = 0; mf < 2; ++mf) {
                uint32_t ad = aBase + (uint32_t)(mf * 16 * A_STRIDE + ksl * 32);
                asm volatile("ld.shared.b32 %0, [%1];"      : "=r"(a[mf][0]) : "r"(ad));
                asm volatile("ld.shared.b32 %0, [%1];"      : "=r"(a[mf][1]) : "r"(ad + 8 * A_STRIDE));
                asm volatile("ld.shared.b32 %0, [%1];"      : "=r"(a[mf][2]) : "r"(ad + 16));
                asm volatile("ld.shared.b32 %0, [%1];"      : "=r"(a[mf][3]) : "r"(ad + 8 * A_STRIDE + 16));
            }
            #pragma unroll
            for (int nf = 0; nf < 8; ++nf) {
                uint32_t b[2];
                uint32_t bd = bBase + (uint32_t)((ksl * 32 + nf) * 256);
                asm volatile("ld.shared.v2.b32 {%0,%1}, [%2];" : "=r"(b[0]), "=r"(b[1]) : "r"(bd));
                mma_tf32(acc[0][nf], a[0], b);
                mma_tf32(acc[1][nf], a[1], b);
            }
        }

        if (kc < 7) {
            convert_store_A(smem, nxt, tid, f0, f1);
            CP_WAIT0;
            __syncthreads();
        }
    }
}

// ---------------------------------------------------------------------------
// QKV GEMM. grid (250, 3), 256 threads. CTA tile 64 x 256.
// ---------------------------------------------------------------------------
__global__ __launch_bounds__(256, 2) void qkv_mm(const float* __restrict__ x) {
    extern __shared__ char smem[];
    uint32_t sb = smem_u32(smem);
    int tid = threadIdx.x;
    int m0 = blockIdx.x * 64;
    int mat = blockIdx.y;

    float acc[2][8][4];
    #pragma unroll
    for (int mf = 0; mf < 2; ++mf)
        #pragma unroll
        for (int nf = 0; nf < 8; ++nf)
            #pragma unroll
            for (int p = 0; p < 4; ++p) acc[mf][nf][p] = 0.0f;

    gemm_tile(smem, sb, x, m0, mat, tid, acc);

    int lane = tid & 31, w = tid >> 5;
    int warp_m = w & 1, warp_n = w >> 1;
    int qrow = lane >> 2, qcol = lane & 3;
    float* out = mat == 0 ? g_q : mat == 1 ? g_k : g_v;

    #pragma unroll
    for (int mf = 0; mf < 2; ++mf) {
        int r0 = m0 + warp_m * 32 + mf * 16 + qrow;
        #pragma unroll
        for (int nf = 0; nf < 8; ++nf) {
            int c = warp_n * 64 + nf * 8 + qcol * 2;
            *(float2*)(out + (size_t)r0 * HD + c)       = make_float2(acc[mf][nf][0], acc[mf][nf][1]);
            *(float2*)(out + (size_t)(r0 + 8) * HD + c) = make_float2(acc[mf][nf][2], acc[mf][nf][3]);
        }
    }
}

// ---------------------------------------------------------------------------
// Edge GEMM + transposed fused epilogue (software-pipelined gathers).
// grid 4000, 256 threads. Each CTA: 64 edges x 256 cols.
// ---------------------------------------------------------------------------
__global__ __launch_bounds__(256, 2) void edge_mm(const float* __restrict__ edge_attr,
                                                  const int* __restrict__ ei,
                                                  const float* __restrict__ coords,
                                                  const float* __restrict__ We,
                                                  float* __restrict__ eout) {
    extern __shared__ char smem[];
    uint32_t sb = smem_u32(smem);
    int tid = threadIdx.x;
    int m0 = blockIdx.x * 64;

    int*   sSrc = (int*)(smem + SM_SRC);
    int*   sDst = (int*)(smem + SM_DST);
    float* sDist = (float*)(smem + SM_DIST);

    if (tid < 64) {
        int s = ei[m0 + tid];
        int d = ei[NEDGES + m0 + tid];
        sSrc[tid] = s; sDst[tid] = d;
        float dx = coords[3 * s + 0] - coords[3 * d + 0];
        float dy = coords[3 * s + 1] - coords[3 * d + 1];
        float dz = coords[3 * s + 2] - coords[3 * d + 2];
        sDist[tid] = 0.1f * sqrtf(dx * dx + dy * dy + dz * dz);
    }
    __syncthreads();

    float acc[2][8][4];
    #pragma unroll
    for (int mf = 0; mf < 2; ++mf)
        #pragma unroll
        for (int nf = 0; nf < 8; ++nf)
            #pragma unroll
            for (int p = 0; p < 4; ++p) acc[mf][nf][p] = 0.0f;

    gemm_tile(smem, sb, edge_attr, m0, 3, tid, acc);

    int lane = tid & 31, w = tid >> 5;
    int warp_m = w & 1, warp_n = w >> 1;
    int qrow = lane >> 2, qcol = lane & 3;

    // ---- stage raw acc into smem alpha tile [64][264] (reuses A/B bufs) ----
    __syncthreads();
    float* alpha = (float*)(smem + SM_ALPHA);
    #pragma unroll
    for (int mf = 0; mf < 2; ++mf) {
        int r0 = warp_m * 32 + mf * 16 + qrow;
        #pragma unroll
        for (int nf = 0; nf < 8; ++nf) {
            int c = warp_n * 64 + nf * 8 + qcol * 2;
            *(float2*)&alpha[r0 * ALPHA_STRIDE + c]       = make_float2(acc[mf][nf][0], acc[mf][nf][1]);
            *(float2*)&alpha[(r0 + 8) * ALPHA_STRIDE + c] = make_float2(acc[mf][nf][2], acc[mf][nf][3]);
        }
    }
    __syncthreads();

    // ---- transposed epilogue: warp w handles edges w*8 .. w*8+7,
    //      with depth-1 software prefetch of the gather loads ----
    const float invs = 0.17677669529663687f;   // 1/sqrt(32)
    int c0 = lane * 4;
    int c1 = 128 + lane * 4;
    int h0 = lane >> 3;
    float4 wlA = *(const float4*)(We + (size_t)DIN * HD + c0);
    float4 wlB = *(const float4*)(We + (size_t)DIN * HD + c1);

    // prefetch edge 0
    int e = w * 8;
    int src = sSrc[e], dst = sDst[e];
    float4 dA = *(const float4*)&alpha[e * ALPHA_STRIDE + c0];
    float4 dB = *(const float4*)&alpha[e * ALPHA_STRIDE + c1];
    float4 kA = *(const float4*)(g_k + (size_t)src * HD + c0);
    float4 kB = *(const float4*)(g_k + (size_t)src * HD + c1);
    float4 qA = *(const float4*)(g_q + (size_t)dst * HD + c0);
    float4 qB = *(const float4*)(g_q + (size_t)dst * HD + c1);
    float4 vA = *(const float4*)(g_v + (size_t)src * HD + c0);
    float4 vB = *(const float4*)(g_v + (size_t)src * HD + c1);

    #pragma unroll
    for (int i = 0; i < 8; ++i) {
        int ecur = w * 8 + i;
        int scur = src, dcur = dst;
        float4 cdA = dA, cdB = dB, ckA = kA, ckB = kB, cqA = qA, cqB = qB, cvA = vA, cvB = vB;
        if (i < 7) {
            int en = ecur + 1;
            src = sSrc[en]; dst = sDst[en];
            dA = *(const float4*)&alpha[en * ALPHA_STRIDE + c0];
            dB = *(const float4*)&alpha[en * ALPHA_STRIDE + c1];
            kA = *(const float4*)(g_k + (size_t)src * HD + c0);
            kB = *(const float4*)(g_k + (size_t)src * HD + c1);
            qA = *(const float4*)(g_q + (size_t)dst * HD + c0);
            qB = *(const float4*)(g_q + (size_t)dst * HD + c1);
            vA = *(const float4*)(g_v + (size_t)src * HD + c0);
            vB = *(const float4*)(g_v + (size_t)src * HD + c1);
        }

        float de = sDist[ecur];
        float4 aA, aB;
        float s;
        s = fminf(5.0f, fmaxf(-5.0f, ckA.x * cqA.x * invs)); aA.x = s * (cdA.x + de * wlA.x);
        s = fminf(5.0f, fmaxf(-5.0f, ckA.y * cqA.y * invs)); aA.y = s * (cdA.y + de * wlA.y);
        s = fminf(5.0f, fmaxf(-5.0f, ckA.z * cqA.z * invs)); aA.z = s * (cdA.z + de * wlA.z);
        s = fminf(5.0f, fmaxf(-5.0f, ckA.w * cqA.w * invs)); aA.w = s * (cdA.w + de * wlA.w);
        s = fminf(5.0f, fmaxf(-5.0f, ckB.x * cqB.x * invs)); aB.x = s * (cdB.x + de * wlB.x);
        s = fminf(5.0f, fmaxf(-5.0f, ckB.y * cqB.y * invs)); aB.y = s * (cdB.y + de * wlB.y);
        s = fminf(5.0f, fmaxf(-5.0f, ckB.z * cqB.z * invs)); aB.z = s * (cdB.z + de * wlB.z);
        s = fminf(5.0f, fmaxf(-5.0f, ckB.w * cqB.w * invs)); aB.w = s * (cdB.w + de * wlB.w);
        float* eo = eout + (size_t)(m0 + ecur) * HD;
        stcs4((float4*)(eo + c0), aA);
        stcs4((float4*)(eo + c1), aB);

        float pA = (aA.x + aA.y) + (aA.z + aA.w);
        float pB = (aB.x + aB.y) + (aB.z + aB.w);
        pA += __shfl_xor_sync(0xffffffffu, pA, 1);
        pB += __shfl_xor_sync(0xffffffffu, pB, 1);
        pA += __shfl_xor_sync(0xffffffffu, pA, 2);
        pB += __shfl_xor_sync(0xffffffffu, pB, 2);
        pA += __shfl_xor_sync(0xffffffffu, pA, 4);
        pB += __shfl_xor_sync(0xffffffffu, pB, 4);
        float axA = expf(fminf(5.0f, fmaxf(-5.0f, pA)));
        float axB = expf(fminf(5.0f, fmaxf(-5.0f, pB)));

        float* wv = g_wV + (size_t)dcur * HD;
        red_v4(wv + c0, make_float4(cvA.x * axA, cvA.y * axA, cvA.z * axA, cvA.w * axA));
        red_v4(wv + c1, make_float4(cvB.x * axB, cvB.y * axB, cvB.z * axB, cvB.w * axB));
        if ((lane & 7) == 0) {
            atomicAdd(&g_z[(size_t)dcur * NH + h0], axA);
            atomicAdd(&g_z[(size_t)dcur * NH + 4 + h0], axB);
        }
    }
}

// ---------------------------------------------------------------------------
__global__ void finalize_kernel(float4* __restrict__ hout4) {
    int i = blockIdx.x * blockDim.x + threadIdx.x;
    if (i < NNODES * HD / 4) {
        int base = i * 4;
        int n = base >> 8;
        int h = (base & 255) >> 5;
        float4 wv = ((const float4*)g_wV)[i];
        float inv = 1.0f / (g_z[n * NH + h] + 1e-6f);
        hout4[i] = make_float4(wv.x * inv, wv.y * inv, wv.z * inv, wv.w * inv);
    }
}

// ---------------------------------------------------------------------------
extern "C" void kernel_launch(void* const* d_in, const int* in_sizes, int n_in,
                              void* d_out, int out_size)
{
    const float* x         = (const float*)d_in[0];
    const float* edge_attr = (const float*)d_in[1];
    const int*   ei        = (const int*)d_in[2];
    const float* coords    = (const float*)d_in[3];
    const float* Wq        = (const float*)d_in[4];
    const float* Wk        = (const float*)d_in[5];
    const float* Wv        = (const float*)d_in[6];
    const float* We        = (const float*)d_in[7];

    float* out  = (float*)d_out;
    float* hout = out;
    float* eout = out + (size_t)NNODES * HD;
    float* cout = eout + (size_t)NEDGES * HD;

    static bool attr_set = false;
    if (!attr_set) {
        cudaFuncSetAttribute(qkv_mm,  cudaFuncAttributeMaxDynamicSharedMemorySize, SM_TOTAL);
        cudaFuncSetAttribute(edge_mm, cudaFuncAttributeMaxDynamicSharedMemorySize, SM_TOTAL);
        attr_set = true;
    }

    init_kernel<<<4000, 256>>>((const float4*)coords, (float4*)cout, Wq, Wk, Wv, We);
    qkv_mm<<<dim3(250, 3), 256, SM_TOTAL>>>(x);
    edge_mm<<<4000, 256, SM_TOTAL>>>(edge_attr, ei, coords, We, eout);
    finalize_kernel<<<(NNODES * HD / 4 + 255) / 256, 256>>>((float4*)hout);
}